// round 14
// baseline (speedup 1.0000x reference)
#include <cuda_runtime.h>

// MySoftBCELoss: B=524288, C=64, f32 -> scalar f32.
// l = argmax(target_row); per_sample = t[l]*log(clip(sig(x[l]))) + log(clip(sig(-x[0])))
// out = -mean(per_sample)
// FINAL (R9 shape; best measured 37.34us, reproduced 37.38/37.60 = noise):
//   - 592 persistent CTAs (exactly 4/SM on 148 SMs) — load-bearing (R7: other
//     grids regress); grid-stride interleaved 16-row tiles.
//   - 16 front-batched coalesced target rows per warp-iter (4KB in flight),
//     evict_first streaming (zero reuse).
//   - argmax via ONE REDUX per row on packed key (value | 63-idx): single
//     warp-op yields max value AND first-max index (jnp.argmax semantics).
//   - x0 prefetch issued first; batched post-chain gathers (R12: interleaving
//     them into the REDUX chain regresses).
//   - single fused kernel, last-block ticket finalize, graph-replay-safe.
// Measured floor: ~239MB irreducible DRAM traffic/pass @ ~6.4TB/s NAT (~80% of
// HBM spec). All traffic- and issue-side levers tested and closed (R3,R4,R6,
// R7,R11,R12 post-mortems).

static constexpr int B_ROWS        = 524288;
static constexpr int C_COLS        = 64;
static constexpr int ROWS_PER_TILE = 16;
static constexpr int NTILES        = B_ROWS / ROWS_PER_TILE;      // 32768
static constexpr int THREADS       = 256;
static constexpr int WARPS_PER_BLOCK = THREADS / 32;              // 8
static constexpr int GRID          = 592;                         // 4 CTAs x 148 SMs
static constexpr int TOTAL_WARPS   = GRID * WARPS_PER_BLOCK;      // 4736

__device__ double   g_accum;    // zero at module load; reset by last block each replay
__device__ unsigned g_count;

__global__ __launch_bounds__(THREADS, 4)
void softbce_persistent_kernel(const float* __restrict__ logits,
                               const float* __restrict__ target,
                               float* __restrict__ out) {
    const int lane = threadIdx.x & 31;
    const int wid  = threadIdx.x >> 5;
    const int gw   = blockIdx.x * WARPS_PER_BLOCK + wid;

    float partial = 0.0f;

#pragma unroll 1
    for (int tile = gw; tile < NTILES; tile += TOTAL_WARPS) {
        const long long row0 = (long long)tile * ROWS_PER_TILE;
        const float* tp   = target + row0 * C_COLS + lane * 2;
        const float* lrow = logits + (row0 + lane) * C_COLS;   // valid for lane<16

        // ---- x0 prefetch FIRST: longest distance to consumer, warms line 0
        //      of this row's logits for the later dependent gather ----
        float x0 = 0.0f;
        if (lane < ROWS_PER_TILE)
            x0 = __ldg(lrow);

        // ---- 16 coalesced target rows, front-batched (4KB/warp in flight),
        //      streaming (evict-first: zero reuse) ----
        float2 v[ROWS_PER_TILE];
#pragma unroll
        for (int k = 0; k < ROWS_PER_TILE; k++)
            v[k] = __ldcs(reinterpret_cast<const float2*>(tp + k * C_COLS));

        // ---- Argmax: ONE REDUX per row on a packed key ----
        // target in [0,1) -> positive float bit order == value order.
        // key = (bits & ~0x3F) | (63 - col): ties -> smallest col (jnp.argmax
        // first-occurrence), value truncation error <= 2^-18 relative.
        unsigned my_key = 0;
#pragma unroll
        for (int k = 0; k < ROWS_PER_TILE; k++) {
            unsigned kx = (__float_as_uint(v[k].x) & 0xFFFFFFC0u) | (unsigned)(63 - 2 * lane);
            unsigned ky = (__float_as_uint(v[k].y) & 0xFFFFFFC0u) | (unsigned)(62 - 2 * lane);
            unsigned loc = kx > ky ? kx : ky;
            unsigned mx  = __reduce_max_sync(0xffffffffu, loc);
            if (lane == k) my_key = mx;
        }

        // ---- Lanes 0..15 finalize one row each (batched gathers) ----
        if (lane < ROWS_PER_TILE) {
            int   idx  = 63 - (int)(my_key & 63u);
            float tval = __uint_as_float(my_key & 0xFFFFFFC0u);
            float xl = __ldg(lrow + idx);
            float pl = 1.0f / (1.0f + __expf(-xl));            // sigmoid(xl)
            pl = fminf(fmaxf(pl, 1e-7f), 1.0f - 1e-7f);
            float q0 = 1.0f / (1.0f + __expf(x0));             // 1 - sigmoid(x0)
            q0 = fminf(fmaxf(q0, 1e-7f), 1.0f - 1e-7f);
            partial += tval * __logf(pl) + __logf(q0);
        }
    }

    // ---- One block reduction total ----
    partial += __shfl_down_sync(0xffffffffu, partial, 8);
    partial += __shfl_down_sync(0xffffffffu, partial, 4);
    partial += __shfl_down_sync(0xffffffffu, partial, 2);
    partial += __shfl_down_sync(0xffffffffu, partial, 1);

    __shared__ float s_warp[WARPS_PER_BLOCK];
    if (lane == 0) s_warp[wid] = partial;
    __syncthreads();

    if (wid == 0) {
        float s = (lane < WARPS_PER_BLOCK) ? s_warp[lane] : 0.0f;
        s += __shfl_down_sync(0xffffffffu, s, 4);
        s += __shfl_down_sync(0xffffffffu, s, 2);
        s += __shfl_down_sync(0xffffffffu, s, 1);
        if (lane == 0) {
            atomicAdd(&g_accum, (double)s);
            __threadfence();
            unsigned ticket = atomicAdd(&g_count, 1u);
            if (ticket == (unsigned)(GRID - 1)) {
                __threadfence();
                double total = atomicAdd(&g_accum, 0.0);   // coherent read
                out[0] = (float)(-total / (double)B_ROWS);
                g_accum = 0.0;                              // reset for next replay
                g_count = 0u;
            }
        }
    }
}

extern "C" void kernel_launch(void* const* d_in, const int* in_sizes, int n_in,
                              void* d_out, int out_size) {
    const float* logits = (const float*)d_in[0];
    const float* target = (const float*)d_in[1];
    float* out = (float*)d_out;
    softbce_persistent_kernel<<<GRID, THREADS>>>(logits, target, out);
}

// round 15
// speedup vs baseline: 1.0009x; 1.0009x over previous
#include <cuda_runtime.h>

// MySoftBCELoss: B=524288, C=64, f32 -> scalar f32.
// l = argmax(target_row); per_sample = t[l]*log(clip(sig(x[l]))) + log(clip(sig(-x[0])))
// out = -mean(per_sample)
//
// FINAL KERNEL (R9 shape; measured 37.34/37.38/37.60/37.63us, sigma~0.15us):
//   - 592 persistent CTAs (exactly 4/SM on 148 SMs) — load-bearing (R7: other
//     grids regress); grid-stride interleaved 16-row tiles.
//   - 16 front-batched coalesced target rows per warp-iter (4KB in flight),
//     evict_first streaming (zero reuse).
//   - argmax via ONE REDUX per row on packed key (value | 63-idx): a single
//     warp-op yields max value AND first-max index (jnp.argmax semantics);
//     6-bit mantissa truncation error <= 2^-18 relative.
//   - x0 prefetch issued first; batched post-chain gathers (R12: interleaving
//     regresses); single fused kernel with last-block ticket finalize.
//
// Why this is the floor (session evidence):
//   byte floor ~239MB/pass = target 134MB (mandatory) + logits 1.508 DRAM
//   lines/row (x0 line + gather line-1 w/ p=32/63); invariant under all load
//   policies (R4, R11), occupancy 39-94% (R2/R3), layout (R7), pipelining
//   (R3), issue shaping (R6, R12). Served at ~6.4TB/s NAT (~80% HBM spec),
//   HBM-scheduling-bound with 42% scattered-line component.

static constexpr int B_ROWS        = 524288;
static constexpr int C_COLS        = 64;
static constexpr int ROWS_PER_TILE = 16;
static constexpr int NTILES        = B_ROWS / ROWS_PER_TILE;      // 32768
static constexpr int THREADS       = 256;
static constexpr int WARPS_PER_BLOCK = THREADS / 32;              // 8
static constexpr int GRID          = 592;                         // 4 CTAs x 148 SMs
static constexpr int TOTAL_WARPS   = GRID * WARPS_PER_BLOCK;      // 4736

__device__ double   g_accum;    // zero at module load; reset by last block each replay
__device__ unsigned g_count;

__global__ __launch_bounds__(THREADS, 4)
void softbce_persistent_kernel(const float* __restrict__ logits,
                               const float* __restrict__ target,
                               float* __restrict__ out) {
    const int lane = threadIdx.x & 31;
    const int wid  = threadIdx.x >> 5;
    const int gw   = blockIdx.x * WARPS_PER_BLOCK + wid;

    float partial = 0.0f;

#pragma unroll 1
    for (int tile = gw; tile < NTILES; tile += TOTAL_WARPS) {
        const long long row0 = (long long)tile * ROWS_PER_TILE;
        const float* tp   = target + row0 * C_COLS + lane * 2;
        const float* lrow = logits + (row0 + lane) * C_COLS;   // valid for lane<16

        // ---- x0 prefetch FIRST: longest distance to consumer, warms line 0
        //      of this row's logits for the later dependent gather ----
        float x0 = 0.0f;
        if (lane < ROWS_PER_TILE)
            x0 = __ldg(lrow);

        // ---- 16 coalesced target rows, front-batched (4KB/warp in flight),
        //      streaming (evict-first: zero reuse) ----
        float2 v[ROWS_PER_TILE];
#pragma unroll
        for (int k = 0; k < ROWS_PER_TILE; k++)
            v[k] = __ldcs(reinterpret_cast<const float2*>(tp + k * C_COLS));

        // ---- Argmax: ONE REDUX per row on a packed key ----
        // target in [0,1) -> positive float bit order == value order.
        // key = (bits & ~0x3F) | (63 - col): ties -> smallest col (jnp.argmax
        // first-occurrence).
        unsigned my_key = 0;
#pragma unroll
        for (int k = 0; k < ROWS_PER_TILE; k++) {
            unsigned kx = (__float_as_uint(v[k].x) & 0xFFFFFFC0u) | (unsigned)(63 - 2 * lane);
            unsigned ky = (__float_as_uint(v[k].y) & 0xFFFFFFC0u) | (unsigned)(62 - 2 * lane);
            unsigned loc = kx > ky ? kx : ky;
            unsigned mx  = __reduce_max_sync(0xffffffffu, loc);
            if (lane == k) my_key = mx;
        }

        // ---- Lanes 0..15 finalize one row each (batched gathers) ----
        if (lane < ROWS_PER_TILE) {
            int   idx  = 63 - (int)(my_key & 63u);
            float tval = __uint_as_float(my_key & 0xFFFFFFC0u);
            float xl = __ldg(lrow + idx);
            float pl = 1.0f / (1.0f + __expf(-xl));            // sigmoid(xl)
            pl = fminf(fmaxf(pl, 1e-7f), 1.0f - 1e-7f);
            float q0 = 1.0f / (1.0f + __expf(x0));             // 1 - sigmoid(x0)
            q0 = fminf(fmaxf(q0, 1e-7f), 1.0f - 1e-7f);
            partial += tval * __logf(pl) + __logf(q0);
        }
    }

    // ---- One block reduction total ----
    partial += __shfl_down_sync(0xffffffffu, partial, 8);
    partial += __shfl_down_sync(0xffffffffu, partial, 4);
    partial += __shfl_down_sync(0xffffffffu, partial, 2);
    partial += __shfl_down_sync(0xffffffffu, partial, 1);

    __shared__ float s_warp[WARPS_PER_BLOCK];
    if (lane == 0) s_warp[wid] = partial;
    __syncthreads();

    if (wid == 0) {
        float s = (lane < WARPS_PER_BLOCK) ? s_warp[lane] : 0.0f;
        s += __shfl_down_sync(0xffffffffu, s, 4);
        s += __shfl_down_sync(0xffffffffu, s, 2);
        s += __shfl_down_sync(0xffffffffu, s, 1);
        if (lane == 0) {
            atomicAdd(&g_accum, (double)s);
            __threadfence();
            unsigned ticket = atomicAdd(&g_count, 1u);
            if (ticket == (unsigned)(GRID - 1)) {
                __threadfence();
                double total = atomicAdd(&g_accum, 0.0);   // coherent read
                out[0] = (float)(-total / (double)B_ROWS);
                g_accum = 0.0;                              // reset for next replay
                g_count = 0u;
            }
        }
    }
}

extern "C" void kernel_launch(void* const* d_in, const int* in_sizes, int n_in,
                              void* d_out, int out_size) {
    const float* logits = (const float*)d_in[0];
    const float* target = (const float*)d_in[1];
    float* out = (float*)d_out;
    softbce_persistent_kernel<<<GRID, THREADS>>>(logits, target, out);
}

// round 16
// speedup vs baseline: 1.0199x; 1.0191x over previous
#include <cuda_runtime.h>

// MySoftBCELoss: B=524288, C=64, f32 -> scalar f32.
// l = argmax(target_row); per_sample = t[l]*log(clip(sig(x[l]))) + log(clip(sig(-x[0])))
// out = -mean(per_sample)
//
// FINAL KERNEL (R9 shape; 5 measurements: 37.34/37.38/37.60/37.63/37.60us,
// mean 37.51, sigma 0.13):
//   - 592 persistent CTAs (exactly 4/SM on 148 SMs) — load-bearing (R7);
//     grid-stride interleaved 16-row tiles.
//   - 16 front-batched coalesced target rows per warp-iter (4KB in flight),
//     evict_first streaming (zero reuse).
//   - argmax via ONE REDUX per row on packed key (value | 63-idx): one
//     warp-op yields max value AND first-max index (jnp.argmax semantics);
//     6-bit mantissa truncation error <= 2^-18 relative.
//   - x0 prefetch issued first; batched post-chain gathers (R12: interleaving
//     regresses); single fused kernel with last-block ticket finalize.
//
// Floor evidence: ~239MB/pass irreducible (target 134MB mandatory + logits
// 1.508 DRAM lines/row), invariant under load policy (R4,R11), occupancy
// 39-94% (R2/R3), layout (R7), pipelining (R3), issue shaping (R6,R12);
// served at ~6.4TB/s NAT (~80% HBM spec), HBM-scheduling-bound.

static constexpr int B_ROWS        = 524288;
static constexpr int C_COLS        = 64;
static constexpr int ROWS_PER_TILE = 16;
static constexpr int NTILES        = B_ROWS / ROWS_PER_TILE;      // 32768
static constexpr int THREADS       = 256;
static constexpr int WARPS_PER_BLOCK = THREADS / 32;              // 8
static constexpr int GRID          = 592;                         // 4 CTAs x 148 SMs
static constexpr int TOTAL_WARPS   = GRID * WARPS_PER_BLOCK;      // 4736

__device__ double   g_accum;    // zero at module load; reset by last block each replay
__device__ unsigned g_count;

__global__ __launch_bounds__(THREADS, 4)
void softbce_persistent_kernel(const float* __restrict__ logits,
                               const float* __restrict__ target,
                               float* __restrict__ out) {
    const int lane = threadIdx.x & 31;
    const int wid  = threadIdx.x >> 5;
    const int gw   = blockIdx.x * WARPS_PER_BLOCK + wid;

    float partial = 0.0f;

#pragma unroll 1
    for (int tile = gw; tile < NTILES; tile += TOTAL_WARPS) {
        const long long row0 = (long long)tile * ROWS_PER_TILE;
        const float* tp   = target + row0 * C_COLS + lane * 2;
        const float* lrow = logits + (row0 + lane) * C_COLS;   // valid for lane<16

        // ---- x0 prefetch FIRST: longest distance to consumer, warms line 0
        //      of this row's logits for the later dependent gather ----
        float x0 = 0.0f;
        if (lane < ROWS_PER_TILE)
            x0 = __ldg(lrow);

        // ---- 16 coalesced target rows, front-batched (4KB/warp in flight),
        //      streaming (evict-first: zero reuse) ----
        float2 v[ROWS_PER_TILE];
#pragma unroll
        for (int k = 0; k < ROWS_PER_TILE; k++)
            v[k] = __ldcs(reinterpret_cast<const float2*>(tp + k * C_COLS));

        // ---- Argmax: ONE REDUX per row on a packed key ----
        // target in [0,1) -> positive float bit order == value order.
        // key = (bits & ~0x3F) | (63 - col): ties -> smallest col (jnp.argmax
        // first-occurrence).
        unsigned my_key = 0;
#pragma unroll
        for (int k = 0; k < ROWS_PER_TILE; k++) {
            unsigned kx = (__float_as_uint(v[k].x) & 0xFFFFFFC0u) | (unsigned)(63 - 2 * lane);
            unsigned ky = (__float_as_uint(v[k].y) & 0xFFFFFFC0u) | (unsigned)(62 - 2 * lane);
            unsigned loc = kx > ky ? kx : ky;
            unsigned mx  = __reduce_max_sync(0xffffffffu, loc);
            if (lane == k) my_key = mx;
        }

        // ---- Lanes 0..15 finalize one row each (batched gathers) ----
        if (lane < ROWS_PER_TILE) {
            int   idx  = 63 - (int)(my_key & 63u);
            float tval = __uint_as_float(my_key & 0xFFFFFFC0u);
            float xl = __ldg(lrow + idx);
            float pl = 1.0f / (1.0f + __expf(-xl));            // sigmoid(xl)
            pl = fminf(fmaxf(pl, 1e-7f), 1.0f - 1e-7f);
            float q0 = 1.0f / (1.0f + __expf(x0));             // 1 - sigmoid(x0)
            q0 = fminf(fmaxf(q0, 1e-7f), 1.0f - 1e-7f);
            partial += tval * __logf(pl) + __logf(q0);
        }
    }

    // ---- One block reduction total ----
    partial += __shfl_down_sync(0xffffffffu, partial, 8);
    partial += __shfl_down_sync(0xffffffffu, partial, 4);
    partial += __shfl_down_sync(0xffffffffu, partial, 2);
    partial += __shfl_down_sync(0xffffffffu, partial, 1);

    __shared__ float s_warp[WARPS_PER_BLOCK];
    if (lane == 0) s_warp[wid] = partial;
    __syncthreads();

    if (wid == 0) {
        float s = (lane < WARPS_PER_BLOCK) ? s_warp[lane] : 0.0f;
        s += __shfl_down_sync(0xffffffffu, s, 4);
        s += __shfl_down_sync(0xffffffffu, s, 2);
        s += __shfl_down_sync(0xffffffffu, s, 1);
        if (lane == 0) {
            atomicAdd(&g_accum, (double)s);
            __threadfence();
            unsigned ticket = atomicAdd(&g_count, 1u);
            if (ticket == (unsigned)(GRID - 1)) {
                __threadfence();
                double total = atomicAdd(&g_accum, 0.0);   // coherent read
                out[0] = (float)(-total / (double)B_ROWS);
                g_accum = 0.0;                              // reset for next replay
                g_count = 0u;
            }
        }
    }
}

extern "C" void kernel_launch(void* const* d_in, const int* in_sizes, int n_in,
                              void* d_out, int out_size) {
    const float* logits = (const float*)d_in[0];
    const float* target = (const float*)d_in[1];
    float* out = (float*)d_out;
    softbce_persistent_kernel<<<GRID, THREADS>>>(logits, target, out);
}